// round 14
// baseline (speedup 1.0000x reference)
#include <cuda_runtime.h>
#include <cuda_bf16.h>
#include <cstdint>

#define BB 8
#define NN 4096
#define MM 1024
#define KK 32
#define CF 64
#define C0IN 67
#define C0 64
#define C1 64
#define C2 128
#define STOT (BB*MM*KK)          // 262144
#define NMB  (STOT/128)          // 2048 mma blocks
#define PSW  16384               // stat partials per channel
#define NQ   (BB*MM)             // 8192
#define EPSBN 1e-5f

typedef unsigned long long ull;

// ---------------- scratch ----------------------------------------------------
__device__ int   g_idx[STOT];
__device__ float g_xT[BB*NN*CF];
__device__ float g_h0[(size_t)C0*STOT];     // [C][S]
__device__ float g_h1[(size_t)C1*STOT];     // [C][S]
__device__ float g_ps1[(size_t)C2*PSW];
__device__ float g_ps2[(size_t)C2*PSW];
__device__ float g_hmax[(size_t)C2*NQ];
__device__ float g_hmin[(size_t)C2*NQ];
__device__ float g_scale[C2];
__device__ float g_shift[C2];

__device__ __forceinline__ uint32_t smem_u32(const void* p) {
    uint32_t a;
    asm("{ .reg .u64 t; cvta.to.shared.u64 t, %1; cvt.u32.u64 %0, t; }" : "=r"(a) : "l"(p));
    return a;
}

// ---------------- mma helpers --------------------------------------------------
__device__ __forceinline__ void ldmA_t(uint32_t (&r)[4], uint32_t addr) {
    asm volatile("ldmatrix.sync.aligned.m8n8.x4.trans.shared.b16 {%0,%1,%2,%3}, [%4];"
        : "=r"(r[0]), "=r"(r[1]), "=r"(r[2]), "=r"(r[3]) : "r"(addr));
}
__device__ __forceinline__ void ldmA_n(uint32_t (&r)[4], uint32_t addr) {
    asm volatile("ldmatrix.sync.aligned.m8n8.x4.shared.b16 {%0,%1,%2,%3}, [%4];"
        : "=r"(r[0]), "=r"(r[1]), "=r"(r[2]), "=r"(r[3]) : "r"(addr));
}
__device__ __forceinline__ void ldmB(uint32_t (&r)[2], uint32_t addr) {
    asm volatile("ldmatrix.sync.aligned.m8n8.x2.shared.b16 {%0,%1}, [%2];"
        : "=r"(r[0]), "=r"(r[1]) : "r"(addr));
}
__device__ __forceinline__ void mma_bf16(float (&c)[4], const uint32_t (&a)[4],
                                         const uint32_t (&b)[2]) {
    asm volatile("mma.sync.aligned.m16n8k16.row.col.f32.bf16.bf16.f32 "
        "{%0,%1,%2,%3}, {%4,%5,%6,%7}, {%8,%9}, {%0,%1,%2,%3};"
        : "+f"(c[0]), "+f"(c[1]), "+f"(c[2]), "+f"(c[3])
        : "r"(a[0]), "r"(a[1]), "r"(a[2]), "r"(a[3]), "r"(b[0]), "r"(b[1]));
}
__device__ __forceinline__ ull pack4bf(float v0, float v1, float v2, float v3) {
    unsigned short u0 = __bfloat16_as_ushort(__float2bfloat16_rn(v0));
    unsigned short u1 = __bfloat16_as_ushort(__float2bfloat16_rn(v1));
    unsigned short u2 = __bfloat16_as_ushort(__float2bfloat16_rn(v2));
    unsigned short u3 = __bfloat16_as_ushort(__float2bfloat16_rn(v3));
    return (ull)u0 | ((ull)u1 << 16) | ((ull)u2 << 32) | ((ull)u3 << 48);
}

// ---------------- transpose x: (B,C,N) -> (B,N,C) ----------------------------
__global__ void k_transpose(const float* __restrict__ x) {
    __shared__ float t[32][33];
    int b  = blockIdx.z;
    int c0 = blockIdx.y * 32;
    int n0 = blockIdx.x * 32;
    int tx = threadIdx.x, ty = threadIdx.y;
#pragma unroll
    for (int r = ty; r < 32; r += 8)
        t[r][tx] = x[(size_t)b*CF*NN + (size_t)(c0 + r)*NN + n0 + tx];
    __syncthreads();
#pragma unroll
    for (int r = ty; r < 32; r += 8)
        g_xT[((size_t)b*NN + n0 + r)*CF + c0 + tx] = t[tx][r];
}

__global__ void k_copyq(const float* __restrict__ q, float* __restrict__ out) {
    int i = blockIdx.x * 256 + threadIdx.x;
    out[i] = q[i];
}

// ---------------- ball query --------------------------------------------------
__global__ void k_ballquery(const float* __restrict__ p, const float* __restrict__ q) {
    extern __shared__ float sp[];
    int* sfound = (int*)(sp + NN*3);
    const int b    = blockIdx.y;
    const int warp = threadIdx.x >> 5;
    const int lane = threadIdx.x & 31;
    const int m    = blockIdx.x * 8 + warp;

    const float* pb = p + (size_t)b * NN * 3;
    for (int i = threadIdx.x; i < NN*3; i += blockDim.x) sp[i] = pb[i];
    __syncthreads();

    const float qx = q[((size_t)b*MM + m)*3 + 0];
    const float qy = q[((size_t)b*MM + m)*3 + 1];
    const float qz = q[((size_t)b*MM + m)*3 + 2];
    const float R2 = 0.04f;

    int cnt = 0;
    for (int j0 = 0; j0 < NN; j0 += 32) {
        int j = j0 + lane;
        float dx = __fadd_rn(sp[3*j+0], -qx);
        float dy = __fadd_rn(sp[3*j+1], -qy);
        float dz = __fadd_rn(sp[3*j+2], -qz);
        float d2 = __fadd_rn(__fadd_rn(__fmul_rn(dx,dx), __fmul_rn(dy,dy)), __fmul_rn(dz,dz));
        bool in = d2 < R2;
        unsigned bal = __ballot_sync(0xffffffffu, in);
        if (in) {
            int slot = cnt + __popc(bal & ((1u << lane) - 1u));
            if (slot < KK) sfound[warp*KK + slot] = j;
        }
        cnt += __popc(bal);
        if (cnt >= KK) break;
    }
    __syncwarp();
    int v;
    if (lane < cnt)      v = sfound[warp*KK + lane];
    else if (cnt > 0)    v = sfound[warp*KK];
    else                 v = 0;
    g_idx[((size_t)b*MM + m)*KK + lane] = v;
}

// =====================================================================
// Shared MMA epilogue: bias + optional h store + stats (+ max/min)
// =====================================================================
template<int NOUT, bool DO_MAX>
__device__ __forceinline__ void mma_epilogue(
    float (&acc)[NOUT/8][4], const float* sbias, float* smx, float* smn,
    float* __restrict__ Hout, int bx)
{
    const int tid = threadIdx.x;
    const int w = tid >> 5, lane = tid & 31;
    const int sBase = bx * 128;
    const int sgrp = lane >> 2;
    const int opair = (lane & 3) * 2;

#pragma unroll
    for (int nt = 0; nt < NOUT/8; nt++) {
        int o0 = nt*8 + opair;
        float d0 = acc[nt][0] + sbias[o0];
        float d1 = acc[nt][1] + sbias[o0+1];
        float d2 = acc[nt][2] + sbias[o0];
        float d3 = acc[nt][3] + sbias[o0+1];

        if (!DO_MAX) {
            int s0 = sBase + w*16 + sgrp;
            Hout[(size_t)o0*STOT + s0]         = d0;
            Hout[(size_t)(o0+1)*STOT + s0]     = d1;
            Hout[(size_t)o0*STOT + s0 + 8]     = d2;
            Hout[(size_t)(o0+1)*STOT + s0 + 8] = d3;
        }

        float ss0 = d0 + d2, ss1 = d1 + d3;
        float qq0 = d0*d0 + d2*d2, qq1 = d1*d1 + d3*d3;
        float mx0 = fmaxf(d0, d2), mx1 = fmaxf(d1, d3);
        float mn0 = fminf(d0, d2), mn1 = fminf(d1, d3);
#pragma unroll
        for (int d = 16; d >= 4; d >>= 1) {
            ss0 += __shfl_down_sync(0xffffffffu, ss0, d);
            ss1 += __shfl_down_sync(0xffffffffu, ss1, d);
            qq0 += __shfl_down_sync(0xffffffffu, qq0, d);
            qq1 += __shfl_down_sync(0xffffffffu, qq1, d);
            if (DO_MAX) {
                mx0 = fmaxf(mx0, __shfl_down_sync(0xffffffffu, mx0, d));
                mx1 = fmaxf(mx1, __shfl_down_sync(0xffffffffu, mx1, d));
                mn0 = fminf(mn0, __shfl_down_sync(0xffffffffu, mn0, d));
                mn1 = fminf(mn1, __shfl_down_sync(0xffffffffu, mn1, d));
            }
        }
        if (lane < 4) {
            int ch = nt*8 + lane*2;
            g_ps1[(size_t)ch*PSW + bx*8 + w]     = ss0;
            g_ps1[(size_t)(ch+1)*PSW + bx*8 + w] = ss1;
            g_ps2[(size_t)ch*PSW + bx*8 + w]     = qq0;
            g_ps2[(size_t)(ch+1)*PSW + bx*8 + w] = qq1;
            if (DO_MAX) {
                smx[w*NOUT + ch]   = mx0;
                smx[w*NOUT + ch+1] = mx1;
                smn[w*NOUT + ch]   = mn0;
                smn[w*NOUT + ch+1] = mn1;
            }
        }
    }

    if (DO_MAX) {
        __syncthreads();
        for (int i = tid; i < NOUT*4; i += 256) {
            int ch = i & (NOUT - 1);
            int qj = i / NOUT;
            float mx = fmaxf(smx[(2*qj)*NOUT + ch], smx[(2*qj+1)*NOUT + ch]);
            float mn = fminf(smn[(2*qj)*NOUT + ch], smn[(2*qj+1)*NOUT + ch]);
            g_hmax[(size_t)ch*NQ + bx*4 + qj] = mx;
            g_hmin[(size_t)ch*NQ + bx*4 + qj] = mn;
        }
    }
}

// =====================================================================
// layer 0 MMA: gather(67ch) -> 64 outs, K used = 80 cols (5 chunks).
// A: [128 samples][cols 0..79] bf16 hi/lo row-major, 256B swizzled rows.
// Balanced staging: thread=(sample,half); each half streams 10 packed
// 4-channel groups. B: [64][cols 0..79] in 256B rows.
// =====================================================================
__global__ void __launch_bounds__(256, 2)
k_mma0(const float* __restrict__ p, const float* __restrict__ q,
       const float* __restrict__ W, const float* __restrict__ bias) {
    extern __shared__ char sm[];
    char* Ahi = sm;                         // [128][256B]
    char* Alo = Ahi + 128*256;
    char* Bhi = Alo + 128*256;              // [64][256B]
    char* Blo = Bhi + 64*256;
    float* sbias = (float*)(Blo + 64*256);

    const int tid = threadIdx.x;
    const int w = tid >> 5, lane = tid & 31;
    const int bx = blockIdx.x;
    const int sBase = bx * 128;

    if (tid < 64) sbias[tid] = bias[tid];

    // stage B: only the 80 columns the MMA reads (c 67..79 zero)
    for (int i = tid; i < 64*80; i += 256) {
        int o = i / 80, c = i - o*80;
        float v = (c < C0IN) ? W[o*C0IN + c] : 0.0f;
        __nv_bfloat16 h = __float2bfloat16_rn(v);
        float hf = __bfloat162float(h);
        uint32_t off = o*256 + ((((c >> 3) ^ (o & 7)) << 4)) + (c & 7) * 2;
        *reinterpret_cast<__nv_bfloat16*>(Bhi + off) = h;
        *reinterpret_cast<__nv_bfloat16*>(Blo + off) = __float2bfloat16_rn(v - hf);
    }

    // stage A: balanced streaming packed stores
    {
        const int s = tid & 127;
        const int half = tid >> 7;              // 0: c 0..39, 1: c 40..79
        const int gs = sBase + s;
        const int b = gs >> 15;
        const int m = (gs & 32767) >> 5;
        const int j = g_idx[gs];
        const float4* xr = reinterpret_cast<const float4*>(g_xT + (((size_t)b*NN + j) << 6));

        const uint32_t rowOff = (uint32_t)s*256;
        const uint32_t sw = (uint32_t)(s & 7);
        // store 4 cols starting at c0 (c0 % 4 == 0)
        #define STORE4(c0, v0, v1, v2, v3) do { \
            float _h0 = __bfloat162float(__float2bfloat16_rn(v0)); \
            float _h1 = __bfloat162float(__float2bfloat16_rn(v1)); \
            float _h2 = __bfloat162float(__float2bfloat16_rn(v2)); \
            float _h3 = __bfloat162float(__float2bfloat16_rn(v3)); \
            uint32_t _off = rowOff + (((((uint32_t)(c0) >> 3) ^ sw) << 4)) + (((c0) & 7) * 2); \
            *reinterpret_cast<ull*>(Ahi + _off) = pack4bf(v0, v1, v2, v3); \
            *reinterpret_cast<ull*>(Alo + _off) = pack4bf((v0)-_h0, (v1)-_h1, (v2)-_h2, (v3)-_h3); \
        } while (0)

        if (half == 0) {
            const float* qp = q + ((size_t)b*MM + m)*3;
            const float* pp = p + ((size_t)b*NN + j)*3;
            float d0 = pp[0] - qp[0];
            float d1 = pp[1] - qp[1];
            float d2 = pp[2] - qp[2];
            float4 cur = xr[0];
            STORE4(0, d0, d1, d2, cur.x);
#pragma unroll
            for (int g = 1; g < 10; g++) {       // c = 4g..4g+3 = x[4g-3..4g]
                float4 nxt = xr[g];
                STORE4(4*g, cur.y, cur.z, cur.w, nxt.x);
                cur = nxt;
            }
        } else {
            float4 cur = xr[9];
#pragma unroll
            for (int g = 10; g < 16; g++) {      // c 40..63
                float4 nxt = xr[g];
                STORE4(4*g, cur.y, cur.z, cur.w, nxt.x);
                cur = nxt;
            }
            STORE4(64, cur.y, cur.z, cur.w, 0.0f);   // c 64..67 (x61..63, pad)
            STORE4(68, 0.0f, 0.0f, 0.0f, 0.0f);
            STORE4(72, 0.0f, 0.0f, 0.0f, 0.0f);
            STORE4(76, 0.0f, 0.0f, 0.0f, 0.0f);
        }
        #undef STORE4
    }
    __syncthreads();

    const uint32_t aHiB = smem_u32(Ahi), aLoB = smem_u32(Alo);
    const uint32_t bHiB = smem_u32(Bhi), bLoB = smem_u32(Blo);

    float acc[8][4];
#pragma unroll
    for (int nt = 0; nt < 8; nt++)
#pragma unroll
        for (int j = 0; j < 4; j++) acc[nt][j] = 0.0f;

    // non-trans A ldmatrix lane roles: row = sample
    const int sA = w*16 + (lane & 15);
    const int cSel = (lane >> 4) << 3;
    const int Bm = (lane & 15) >> 3, Br = lane & 7;

#pragma unroll
    for (int k = 0; k < 5; k++) {
        int cblk = k*16 + cSel;
        uint32_t offA = sA*256 + ((((cblk >> 3) ^ (sA & 7)) << 4));
        uint32_t ah[4], al[4];
        ldmA_n(ah, aHiB + offA);
        ldmA_n(al, aLoB + offA);
        int cB = k*16 + Bm*8;
#pragma unroll
        for (int nt = 0; nt < 8; nt++) {
            int oRow = nt*8 + Br;
            uint32_t offB = oRow*256 + ((((cB >> 3) ^ (oRow & 7)) << 4));
            uint32_t bh[2], bl[2];
            ldmB(bh, bHiB + offB);
            ldmB(bl, bLoB + offB);
            mma_bf16(acc[nt], ah, bh);
            mma_bf16(acc[nt], ah, bl);
            mma_bf16(acc[nt], al, bh);
        }
    }

    mma_epilogue<64, false>(acc, sbias, nullptr, nullptr, g_h0, bx);
}

// =====================================================================
// layers 1/2 MMA (R12 config): 64 in -> NOUT out, K=64. A [c][s] trans.
// =====================================================================
template<int NOUT, bool DO_MAX>
__global__ void __launch_bounds__(256, 2)
k_mma(const float* __restrict__ Hin, float* __restrict__ Hout,
      const float* __restrict__ W, const float* __restrict__ bias) {
    extern __shared__ char sm[];
    __nv_bfloat16* Ahi = (__nv_bfloat16*)sm;            // [64][128]
    __nv_bfloat16* Alo = Ahi + 64*128;
    __nv_bfloat16* Bhi = Alo + 64*128;                  // [NOUT][64]
    __nv_bfloat16* Blo = Bhi + NOUT*64;
    float* sbias = (float*)(Blo + NOUT*64);
    float* scs   = sbias + NOUT;
    float* shs   = scs + 64;
    float* smx   = shs + 64;
    float* smn   = smx + 8*NOUT;

    const int tid = threadIdx.x;
    const int w = tid >> 5, lane = tid & 31;
    const int bx = blockIdx.x;
    const int sBase = bx * 128;

    if (tid < 64) { scs[tid] = g_scale[tid]; shs[tid] = g_shift[tid]; }
    for (int i = tid; i < NOUT; i += 256) sbias[i] = bias[i];

    for (int i = tid; i < NOUT*16; i += 256) {
        int o = i >> 4, c4 = (i & 15) * 4;
        float4 wv = *reinterpret_cast<const float4*>(W + o*64 + c4);
        float h0f = __bfloat162float(__float2bfloat16_rn(wv.x));
        float h1f = __bfloat162float(__float2bfloat16_rn(wv.y));
        float h2f = __bfloat162float(__float2bfloat16_rn(wv.z));
        float h3f = __bfloat162float(__float2bfloat16_rn(wv.w));
        uint32_t off = o*128 + ((((c4 >> 3) ^ (o & 7)) << 4)) + (c4 & 7) * 2;
        *reinterpret_cast<ull*>((char*)Bhi + off) = pack4bf(wv.x, wv.y, wv.z, wv.w);
        *reinterpret_cast<ull*>((char*)Blo + off) =
            pack4bf(wv.x - h0f, wv.y - h1f, wv.z - h2f, wv.w - h3f);
    }

    for (int i = tid; i < 64*32; i += 256) {
        int c = i >> 5, s4 = (i & 31) * 4;
        float4 v = *reinterpret_cast<const float4*>(Hin + (size_t)c*STOT + sBase + s4);
        float sc = scs[c], sh = shs[c];
        float v0 = fmaxf(fmaf(v.x, sc, sh), 0.0f);
        float v1 = fmaxf(fmaf(v.y, sc, sh), 0.0f);
        float v2 = fmaxf(fmaf(v.z, sc, sh), 0.0f);
        float v3 = fmaxf(fmaf(v.w, sc, sh), 0.0f);
        float h0f = __bfloat162float(__float2bfloat16_rn(v0));
        float h1f = __bfloat162float(__float2bfloat16_rn(v1));
        float h2f = __bfloat162float(__float2bfloat16_rn(v2));
        float h3f = __bfloat162float(__float2bfloat16_rn(v3));
        uint32_t off = c*256 + ((((s4 >> 3) ^ (c & 7)) << 4)) + (s4 & 7) * 2;
        *reinterpret_cast<ull*>((char*)Ahi + off) = pack4bf(v0, v1, v2, v3);
        *reinterpret_cast<ull*>((char*)Alo + off) =
            pack4bf(v0 - h0f, v1 - h1f, v2 - h2f, v3 - h3f);
    }
    __syncthreads();

    const uint32_t aHiB = smem_u32(Ahi), aLoB = smem_u32(Alo);
    const uint32_t bHiB = smem_u32(Bhi), bLoB = smem_u32(Blo);

    float acc[NOUT/8][4];
#pragma unroll
    for (int nt = 0; nt < NOUT/8; nt++)
#pragma unroll
        for (int j = 0; j < 4; j++) acc[nt][j] = 0.0f;

    const int Am = lane >> 3, Ar = lane & 7;
    const int sA = w*16 + (Am & 1)*8;
    const int cAadd = (Am >> 1) * 8 + Ar;
    const int Bm = (lane & 15) >> 3, Br = lane & 7;

#pragma unroll
    for (int k = 0; k < 4; k++) {
        int cA = k*16 + cAadd;
        uint32_t offA = cA*256 + ((((sA >> 3) ^ (cA & 7)) << 4));
        uint32_t ah[4], al[4];
        ldmA_t(ah, aHiB + offA);
        ldmA_t(al, aLoB + offA);
        int cB = k*16 + Bm*8;
#pragma unroll
        for (int nt = 0; nt < NOUT/8; nt++) {
            int oRow = nt*8 + Br;
            uint32_t offB = oRow*128 + ((((cB >> 3) ^ (oRow & 7)) << 4));
            uint32_t bh[2], bl[2];
            ldmB(bh, bHiB + offB);
            ldmB(bl, bLoB + offB);
            mma_bf16(acc[nt], ah, bh);
            mma_bf16(acc[nt], ah, bl);
            mma_bf16(acc[nt], al, bh);
        }
    }

    mma_epilogue<NOUT, DO_MAX>(acc, sbias, smx, smn, Hout, bx);
}

// ---------------- stats reduce ------------------------------------------------
__global__ void k_reduce2(const float* __restrict__ gam, const float* __restrict__ bet,
                          int count) {
    __shared__ float s1[256], s2[256];
    const int c = blockIdx.x;
    const int t = threadIdx.x;
    const float* p1 = g_ps1 + (size_t)c*PSW;
    const float* p2 = g_ps2 + (size_t)c*PSW;
    float a = 0.f, b = 0.f;
    for (int i = t; i < count; i += 256) { a += p1[i]; b += p2[i]; }
    s1[t] = a; s2[t] = b;
    __syncthreads();
#pragma unroll
    for (int d = 128; d; d >>= 1) {
        if (t < d) { s1[t] += s1[t+d]; s2[t] += s2[t+d]; }
        __syncthreads();
    }
    if (t == 0) {
        const float inv = 1.0f / (float)STOT;
        float mu  = s1[0] * inv;
        float var = s2[0] * inv - mu * mu;
        float sc  = gam[c] * rsqrtf(var + EPSBN);
        g_scale[c] = sc;
        g_shift[c] = bet[c] - mu * sc;
    }
}

// ---------------- finalize: affine extreme + relu -> out (B,C2,M) -------------
__global__ void k_finalmax(float* __restrict__ out) {
    const int t = blockIdx.x * 256 + threadIdx.x;
    const int m = t & 1023;
    const int c = (t >> 10) & 127;
    const int b = t >> 17;
    const int qidx = (b << 10) + m;
    const float sc = g_scale[c], sh = g_shift[c];
    float ext = (sc >= 0.0f) ? g_hmax[(size_t)c*NQ + qidx] : g_hmin[(size_t)c*NQ + qidx];
    float v = fmaxf(fmaf(ext, sc, sh), 0.0f);
    out[(size_t)BB*MM*3 + (((size_t)b*C2 + c) << 10) + m] = v;
}

// ---------------- launch --------------------------------------------------------
extern "C" void kernel_launch(void* const* d_in, const int* in_sizes, int n_in,
                              void* d_out, int out_size) {
    const float* p   = (const float*)d_in[0];
    const float* q   = (const float*)d_in[1];
    const float* x   = (const float*)d_in[2];
    const float* W0  = (const float*)d_in[3];
    const float* b0  = (const float*)d_in[4];
    const float* g0  = (const float*)d_in[5];
    const float* be0 = (const float*)d_in[6];
    const float* W1  = (const float*)d_in[7];
    const float* b1  = (const float*)d_in[8];
    const float* g1  = (const float*)d_in[9];
    const float* be1 = (const float*)d_in[10];
    const float* W2  = (const float*)d_in[11];
    const float* b2  = (const float*)d_in[12];
    const float* g2  = (const float*)d_in[13];
    const float* be2 = (const float*)d_in[14];
    float* out = (float*)d_out;

    float *h0p, *h1p;
    cudaGetSymbolAddress((void**)&h0p, g_h0);
    cudaGetSymbolAddress((void**)&h1p, g_h1);

    const int bq_smem = NN*3*4 + 8*KK*4;
    const int m0_smem = 2*128*256 + 2*64*256 + 64*4;              // 98560
    const int m1_smem = 2*64*128*2 + 2*64*64*2 + (64+128)*4 + 2*8*64*4;
    const int m2_smem = 2*64*128*2 + 2*128*64*2 + (128+128)*4 + 2*8*128*4;
    cudaFuncSetAttribute(k_ballquery, cudaFuncAttributeMaxDynamicSharedMemorySize, bq_smem);
    cudaFuncSetAttribute(k_mma0, cudaFuncAttributeMaxDynamicSharedMemorySize, m0_smem);
    cudaFuncSetAttribute((const void*)k_mma<64,false>,  cudaFuncAttributeMaxDynamicSharedMemorySize, m1_smem);
    cudaFuncSetAttribute((const void*)k_mma<128,true>,  cudaFuncAttributeMaxDynamicSharedMemorySize, m2_smem);

    k_transpose<<<dim3(NN/32, CF/32, BB), dim3(32, 8)>>>(x);
    k_copyq<<<(BB*MM*3)/256, 256>>>(q, out);
    k_ballquery<<<dim3(MM/8, BB), 256, bq_smem>>>(p, q);

    k_mma0<<<NMB, 256, m0_smem>>>(p, q, W0, b0);
    k_reduce2<<<C0, 256>>>(g0, be0, PSW);

    k_mma<64,false><<<NMB, 256, m1_smem>>>(h0p, h1p, W1, b1);
    k_reduce2<<<C1, 256>>>(g1, be1, PSW);

    k_mma<128,true><<<NMB, 256, m2_smem>>>(h1p, nullptr, W2, b2);
    k_reduce2<<<C2, 256>>>(g2, be2, PSW);

    k_finalmax<<<(BB*C2*MM)/256, 256>>>(out);
}

// round 15
// speedup vs baseline: 1.0536x; 1.0536x over previous
#include <cuda_runtime.h>
#include <cuda_bf16.h>
#include <cstdint>

#define BB 8
#define NN 4096
#define MM 1024
#define KK 32
#define CF 64
#define C0IN 67
#define C0 64
#define C1 64
#define C2 128
#define STOT (BB*MM*KK)          // 262144
#define NMB  (STOT/128)          // 2048 mma blocks
#define PSW  16384               // stat partials per channel
#define NQ   (BB*MM)             // 8192
#define EPSBN 1e-5f

typedef unsigned long long ull;

// ---------------- scratch ----------------------------------------------------
__device__ int   g_idx[STOT];
__device__ float g_xT[BB*NN*CF];
__device__ float g_h0[(size_t)C0*STOT];     // [C][S]
__device__ float g_h1[(size_t)C1*STOT];     // [C][S]
__device__ float g_ps1[(size_t)C2*PSW];
__device__ float g_ps2[(size_t)C2*PSW];
__device__ float g_hmax[(size_t)C2*NQ];
__device__ float g_hmin[(size_t)C2*NQ];
__device__ float g_scale[C2];
__device__ float g_shift[C2];

__device__ __forceinline__ uint32_t smem_u32(const void* p) {
    uint32_t a;
    asm("{ .reg .u64 t; cvta.to.shared.u64 t, %1; cvt.u32.u64 %0, t; }" : "=r"(a) : "l"(p));
    return a;
}

// ---------------- mma helpers --------------------------------------------------
__device__ __forceinline__ void ldmA_t(uint32_t (&r)[4], uint32_t addr) {
    asm volatile("ldmatrix.sync.aligned.m8n8.x4.trans.shared.b16 {%0,%1,%2,%3}, [%4];"
        : "=r"(r[0]), "=r"(r[1]), "=r"(r[2]), "=r"(r[3]) : "r"(addr));
}
// x4 B load: serves two consecutive nt tiles (4 regs)
__device__ __forceinline__ void ldmB4(uint32_t (&r)[4], uint32_t addr) {
    asm volatile("ldmatrix.sync.aligned.m8n8.x4.shared.b16 {%0,%1,%2,%3}, [%4];"
        : "=r"(r[0]), "=r"(r[1]), "=r"(r[2]), "=r"(r[3]) : "r"(addr));
}
__device__ __forceinline__ void mma_bf16(float (&c)[4], const uint32_t* a,
                                         const uint32_t* b) {
    asm volatile("mma.sync.aligned.m16n8k16.row.col.f32.bf16.bf16.f32 "
        "{%0,%1,%2,%3}, {%4,%5,%6,%7}, {%8,%9}, {%0,%1,%2,%3};"
        : "+f"(c[0]), "+f"(c[1]), "+f"(c[2]), "+f"(c[3])
        : "r"(a[0]), "r"(a[1]), "r"(a[2]), "r"(a[3]), "r"(b[0]), "r"(b[1]));
}
__device__ __forceinline__ ull pack4bf(float v0, float v1, float v2, float v3) {
    unsigned short u0 = __bfloat16_as_ushort(__float2bfloat16_rn(v0));
    unsigned short u1 = __bfloat16_as_ushort(__float2bfloat16_rn(v1));
    unsigned short u2 = __bfloat16_as_ushort(__float2bfloat16_rn(v2));
    unsigned short u3 = __bfloat16_as_ushort(__float2bfloat16_rn(v3));
    return (ull)u0 | ((ull)u1 << 16) | ((ull)u2 << 32) | ((ull)u3 << 48);
}
// elementwise hi/lo split store into [row][128-col] bf16 tile, 256B swizzled rows
__device__ __forceinline__ void splitA(char* hi, char* lo, int r, int s, float v) {
    __nv_bfloat16 h = __float2bfloat16_rn(v);
    float hf = __bfloat162float(h);
    uint32_t off = r*256 + ((((s >> 3) ^ (r & 7)) << 4)) + (s & 7) * 2;
    *reinterpret_cast<__nv_bfloat16*>(hi + off) = h;
    *reinterpret_cast<__nv_bfloat16*>(lo + off) = __float2bfloat16_rn(v - hf);
}

// ---------------- transpose x: (B,C,N) -> (B,N,C) ----------------------------
__global__ void k_transpose(const float* __restrict__ x) {
    __shared__ float t[32][33];
    int b  = blockIdx.z;
    int c0 = blockIdx.y * 32;
    int n0 = blockIdx.x * 32;
    int tx = threadIdx.x, ty = threadIdx.y;
#pragma unroll
    for (int r = ty; r < 32; r += 8)
        t[r][tx] = x[(size_t)b*CF*NN + (size_t)(c0 + r)*NN + n0 + tx];
    __syncthreads();
#pragma unroll
    for (int r = ty; r < 32; r += 8)
        g_xT[((size_t)b*NN + n0 + r)*CF + c0 + tx] = t[tx][r];
}

__global__ void k_copyq(const float* __restrict__ q, float* __restrict__ out) {
    int i = blockIdx.x * 256 + threadIdx.x;
    out[i] = q[i];
}

// ---------------- ball query --------------------------------------------------
__global__ void k_ballquery(const float* __restrict__ p, const float* __restrict__ q) {
    extern __shared__ float sp[];
    int* sfound = (int*)(sp + NN*3);
    const int b    = blockIdx.y;
    const int warp = threadIdx.x >> 5;
    const int lane = threadIdx.x & 31;
    const int m    = blockIdx.x * 8 + warp;

    const float* pb = p + (size_t)b * NN * 3;
    for (int i = threadIdx.x; i < NN*3; i += blockDim.x) sp[i] = pb[i];
    __syncthreads();

    const float qx = q[((size_t)b*MM + m)*3 + 0];
    const float qy = q[((size_t)b*MM + m)*3 + 1];
    const float qz = q[((size_t)b*MM + m)*3 + 2];
    const float R2 = 0.04f;

    int cnt = 0;
    for (int j0 = 0; j0 < NN; j0 += 32) {
        int j = j0 + lane;
        float dx = __fadd_rn(sp[3*j+0], -qx);
        float dy = __fadd_rn(sp[3*j+1], -qy);
        float dz = __fadd_rn(sp[3*j+2], -qz);
        float d2 = __fadd_rn(__fadd_rn(__fmul_rn(dx,dx), __fmul_rn(dy,dy)), __fmul_rn(dz,dz));
        bool in = d2 < R2;
        unsigned bal = __ballot_sync(0xffffffffu, in);
        if (in) {
            int slot = cnt + __popc(bal & ((1u << lane) - 1u));
            if (slot < KK) sfound[warp*KK + slot] = j;
        }
        cnt += __popc(bal);
        if (cnt >= KK) break;
    }
    __syncwarp();
    int v;
    if (lane < cnt)      v = sfound[warp*KK + lane];
    else if (cnt > 0)    v = sfound[warp*KK];
    else                 v = 0;
    g_idx[((size_t)b*MM + m)*KK + lane] = v;
}

// =====================================================================
// Shared MMA epilogue: bias + optional h store + stats (+ max/min)
// =====================================================================
template<int NOUT, bool DO_MAX>
__device__ __forceinline__ void mma_epilogue(
    float (&acc)[NOUT/8][4], const float* sbias, float* smx, float* smn,
    float* __restrict__ Hout, int bx)
{
    const int tid = threadIdx.x;
    const int w = tid >> 5, lane = tid & 31;
    const int sBase = bx * 128;
    const int sgrp = lane >> 2;
    const int opair = (lane & 3) * 2;

#pragma unroll
    for (int nt = 0; nt < NOUT/8; nt++) {
        int o0 = nt*8 + opair;
        float d0 = acc[nt][0] + sbias[o0];
        float d1 = acc[nt][1] + sbias[o0+1];
        float d2 = acc[nt][2] + sbias[o0];
        float d3 = acc[nt][3] + sbias[o0+1];

        if (!DO_MAX) {
            int s0 = sBase + w*16 + sgrp;
            Hout[(size_t)o0*STOT + s0]         = d0;
            Hout[(size_t)(o0+1)*STOT + s0]     = d1;
            Hout[(size_t)o0*STOT + s0 + 8]     = d2;
            Hout[(size_t)(o0+1)*STOT + s0 + 8] = d3;
        }

        float ss0 = d0 + d2, ss1 = d1 + d3;
        float qq0 = d0*d0 + d2*d2, qq1 = d1*d1 + d3*d3;
        float mx0 = fmaxf(d0, d2), mx1 = fmaxf(d1, d3);
        float mn0 = fminf(d0, d2), mn1 = fminf(d1, d3);
#pragma unroll
        for (int d = 16; d >= 4; d >>= 1) {
            ss0 += __shfl_down_sync(0xffffffffu, ss0, d);
            ss1 += __shfl_down_sync(0xffffffffu, ss1, d);
            qq0 += __shfl_down_sync(0xffffffffu, qq0, d);
            qq1 += __shfl_down_sync(0xffffffffu, qq1, d);
            if (DO_MAX) {
                mx0 = fmaxf(mx0, __shfl_down_sync(0xffffffffu, mx0, d));
                mx1 = fmaxf(mx1, __shfl_down_sync(0xffffffffu, mx1, d));
                mn0 = fminf(mn0, __shfl_down_sync(0xffffffffu, mn0, d));
                mn1 = fminf(mn1, __shfl_down_sync(0xffffffffu, mn1, d));
            }
        }
        if (lane < 4) {
            int ch = nt*8 + lane*2;
            g_ps1[(size_t)ch*PSW + bx*8 + w]     = ss0;
            g_ps1[(size_t)(ch+1)*PSW + bx*8 + w] = ss1;
            g_ps2[(size_t)ch*PSW + bx*8 + w]     = qq0;
            g_ps2[(size_t)(ch+1)*PSW + bx*8 + w] = qq1;
            if (DO_MAX) {
                smx[w*NOUT + ch]   = mx0;
                smx[w*NOUT + ch+1] = mx1;
                smn[w*NOUT + ch]   = mn0;
                smn[w*NOUT + ch+1] = mn1;
            }
        }
    }

    if (DO_MAX) {
        __syncthreads();
        for (int i = tid; i < NOUT*4; i += 256) {
            int ch = i & (NOUT - 1);
            int qj = i / NOUT;
            float mx = fmaxf(smx[(2*qj)*NOUT + ch], smx[(2*qj+1)*NOUT + ch]);
            float mn = fminf(smn[(2*qj)*NOUT + ch], smn[(2*qj+1)*NOUT + ch]);
            g_hmax[(size_t)ch*NQ + bx*4 + qj] = mx;
            g_hmin[(size_t)ch*NQ + bx*4 + qj] = mn;
        }
    }
}

// =====================================================================
// layer 0 MMA (R12 staging): gather -> [c][s] columns, trans ldmatrix A.
// A: [80][128] bf16 hi/lo, 256B swizzled rows. B: [64][128] 256B rows.
// B loads upgraded to x4 (two nt per load).
// =====================================================================
__global__ void __launch_bounds__(256, 2)
k_mma0(const float* __restrict__ p, const float* __restrict__ q,
       const float* __restrict__ W, const float* __restrict__ bias) {
    extern __shared__ char sm[];
    char* Ahi = sm;                         // [80][128] bf16 (20480B)
    char* Alo = Ahi + 80*256;
    char* Bhi = Alo + 80*256;               // [64][128] bf16 (16384B)
    char* Blo = Bhi + 64*256;
    float* sbias = (float*)(Blo + 64*256);

    const int tid = threadIdx.x;
    const int w = tid >> 5, lane = tid & 31;
    const int bx = blockIdx.x;
    const int sBase = bx * 128;

    if (tid < 64) sbias[tid] = bias[tid];

    // stage B: W0[o][c] (stride 67), pad c 67..127 with zeros
    for (int i = tid; i < 64*128; i += 256) {
        int o = i >> 7, c = i & 127;
        float v = (c < C0IN) ? W[o*C0IN + c] : 0.0f;
        __nv_bfloat16 h = __float2bfloat16_rn(v);
        float hf = __bfloat162float(h);
        uint32_t off = o*256 + ((((c >> 3) ^ (o & 7)) << 4)) + (c & 7) * 2;
        *reinterpret_cast<__nv_bfloat16*>(Bhi + off) = h;
        *reinterpret_cast<__nv_bfloat16*>(Blo + off) = __float2bfloat16_rn(v - hf);
    }
    // zero-pad A rows 67..79
    for (int i = tid; i < 13*128; i += 256) {
        int r = 67 + (i >> 7), s = i & 127;
        uint32_t off = r*256 + ((((s >> 3) ^ (r & 7)) << 4)) + (s & 7) * 2;
        *reinterpret_cast<__nv_bfloat16*>(Ahi + off) = __float2bfloat16_rn(0.0f);
        *reinterpret_cast<__nv_bfloat16*>(Alo + off) = __float2bfloat16_rn(0.0f);
    }
    // stage A: gather; 2 threads per sample (half = channel split)
    {
        const int s = tid & 127;
        const int half = tid >> 7;
        const int gs = sBase + s;
        const int b = gs >> 15;
        const int m = (gs & 32767) >> 5;
        const int j = g_idx[gs];
        const float4* xr = reinterpret_cast<const float4*>(g_xT + (((size_t)b*NN + j) << 6));
        if (half == 0) {
            const float* qp = q + ((size_t)b*MM + m)*3;
            const float* pp = p + ((size_t)b*NN + j)*3;
            splitA(Ahi, Alo, 0, s, pp[0] - qp[0]);
            splitA(Ahi, Alo, 1, s, pp[1] - qp[1]);
            splitA(Ahi, Alo, 2, s, pp[2] - qp[2]);
#pragma unroll
            for (int c4 = 0; c4 < 8; c4++) {
                float4 v = xr[c4];
                splitA(Ahi, Alo, 3 + 4*c4 + 0, s, v.x);
                splitA(Ahi, Alo, 3 + 4*c4 + 1, s, v.y);
                splitA(Ahi, Alo, 3 + 4*c4 + 2, s, v.z);
                splitA(Ahi, Alo, 3 + 4*c4 + 3, s, v.w);
            }
        } else {
#pragma unroll
            for (int c4 = 8; c4 < 16; c4++) {
                float4 v = xr[c4];
                splitA(Ahi, Alo, 3 + 4*c4 + 0, s, v.x);
                splitA(Ahi, Alo, 3 + 4*c4 + 1, s, v.y);
                splitA(Ahi, Alo, 3 + 4*c4 + 2, s, v.z);
                splitA(Ahi, Alo, 3 + 4*c4 + 3, s, v.w);
            }
        }
    }
    __syncthreads();

    const uint32_t aHiB = smem_u32(Ahi), aLoB = smem_u32(Alo);
    const uint32_t bHiB = smem_u32(Bhi), bLoB = smem_u32(Blo);

    float acc[8][4];
#pragma unroll
    for (int nt = 0; nt < 8; nt++)
#pragma unroll
        for (int j = 0; j < 4; j++) acc[nt][j] = 0.0f;

    const int Am = lane >> 3, Ar = lane & 7;
    const int sA = w*16 + (Am & 1)*8;
    const int cAadd = (Am >> 1) * 8 + Ar;
    // x4 B lane roles: lanes 0-7 mat0=(ntp, cB), 8-15 mat1=(ntp, cB+8),
    //                  16-23 mat2=(ntp+1, cB), 24-31 mat3=(ntp+1, cB+8)
    const int Br  = lane & 7;
    const int Bc  = (lane >> 3) & 1;          // col-half
    const int Bnt = lane >> 4;                // nt offset (0/1)

#pragma unroll
    for (int k = 0; k < 5; k++) {
        int cA = k*16 + cAadd;
        uint32_t offA = cA*256 + ((((sA >> 3) ^ (cA & 7)) << 4));
        uint32_t ah[4], al[4];
        ldmA_t(ah, aHiB + offA);
        ldmA_t(al, aLoB + offA);
        int cB = k*16 + Bc*8;
#pragma unroll
        for (int ntp = 0; ntp < 4; ntp++) {   // nt pair
            int oRow = (2*ntp + Bnt)*8 + Br;
            uint32_t offB = oRow*256 + ((((cB >> 3) ^ (oRow & 7)) << 4));
            uint32_t bh[4], bl[4];
            ldmB4(bh, bHiB + offB);
            ldmB4(bl, bLoB + offB);
            mma_bf16(acc[2*ntp],   ah, bh);
            mma_bf16(acc[2*ntp],   ah, bl);
            mma_bf16(acc[2*ntp],   al, bh);
            mma_bf16(acc[2*ntp+1], ah, bh + 2);
            mma_bf16(acc[2*ntp+1], ah, bl + 2);
            mma_bf16(acc[2*ntp+1], al, bh + 2);
        }
    }

    mma_epilogue<64, false>(acc, sbias, nullptr, nullptr, g_h0, bx);
}

// =====================================================================
// layers 1/2 MMA (R12): 64 in -> NOUT out, K=64. A [c][s] trans; B x4.
// =====================================================================
template<int NOUT, bool DO_MAX>
__global__ void __launch_bounds__(256, 2)
k_mma(const float* __restrict__ Hin, float* __restrict__ Hout,
      const float* __restrict__ W, const float* __restrict__ bias) {
    extern __shared__ char sm[];
    __nv_bfloat16* Ahi = (__nv_bfloat16*)sm;            // [64][128]
    __nv_bfloat16* Alo = Ahi + 64*128;
    __nv_bfloat16* Bhi = Alo + 64*128;                  // [NOUT][64]
    __nv_bfloat16* Blo = Bhi + NOUT*64;
    float* sbias = (float*)(Blo + NOUT*64);
    float* scs   = sbias + NOUT;
    float* shs   = scs + 64;
    float* smx   = shs + 64;
    float* smn   = smx + 8*NOUT;

    const int tid = threadIdx.x;
    const int w = tid >> 5, lane = tid & 31;
    const int bx = blockIdx.x;
    const int sBase = bx * 128;

    if (tid < 64) { scs[tid] = g_scale[tid]; shs[tid] = g_shift[tid]; }
    for (int i = tid; i < NOUT; i += 256) sbias[i] = bias[i];

    for (int i = tid; i < NOUT*16; i += 256) {
        int o = i >> 4, c4 = (i & 15) * 4;
        float4 wv = *reinterpret_cast<const float4*>(W + o*64 + c4);
        float h0f = __bfloat162float(__float2bfloat16_rn(wv.x));
        float h1f = __bfloat162float(__float2bfloat16_rn(wv.y));
        float h2f = __bfloat162float(__float2bfloat16_rn(wv.z));
        float h3f = __bfloat162float(__float2bfloat16_rn(wv.w));
        uint32_t off = o*128 + ((((c4 >> 3) ^ (o & 7)) << 4)) + (c4 & 7) * 2;
        *reinterpret_cast<ull*>((char*)Bhi + off) = pack4bf(wv.x, wv.y, wv.z, wv.w);
        *reinterpret_cast<ull*>((char*)Blo + off) =
            pack4bf(wv.x - h0f, wv.y - h1f, wv.z - h2f, wv.w - h3f);
    }

    for (int i = tid; i < 64*32; i += 256) {
        int c = i >> 5, s4 = (i & 31) * 4;
        float4 v = *reinterpret_cast<const float4*>(Hin + (size_t)c*STOT + sBase + s4);
        float sc = scs[c], sh = shs[c];
        float v0 = fmaxf(fmaf(v.x, sc, sh), 0.0f);
        float v1 = fmaxf(fmaf(v.y, sc, sh), 0.0f);
        float v2 = fmaxf(fmaf(v.z, sc, sh), 0.0f);
        float v3 = fmaxf(fmaf(v.w, sc, sh), 0.0f);
        float h0f = __bfloat162float(__float2bfloat16_rn(v0));
        float h1f = __bfloat162float(__float2bfloat16_rn(v1));
        float h2f = __bfloat162float(__float2bfloat16_rn(v2));
        float h3f = __bfloat162float(__float2bfloat16_rn(v3));
        uint32_t off = c*256 + ((((s4 >> 3) ^ (c & 7)) << 4)) + (s4 & 7) * 2;
        *reinterpret_cast<ull*>((char*)Ahi + off) = pack4bf(v0, v1, v2, v3);
        *reinterpret_cast<ull*>((char*)Alo + off) =
            pack4bf(v0 - h0f, v1 - h1f, v2 - h2f, v3 - h3f);
    }
    __syncthreads();

    const uint32_t aHiB = smem_u32(Ahi), aLoB = smem_u32(Alo);
    const uint32_t bHiB = smem_u32(Bhi), bLoB = smem_u32(Blo);

    float acc[NOUT/8][4];
#pragma unroll
    for (int nt = 0; nt < NOUT/8; nt++)
#pragma unroll
        for (int j = 0; j < 4; j++) acc[nt][j] = 0.0f;

    const int Am = lane >> 3, Ar = lane & 7;
    const int sA = w*16 + (Am & 1)*8;
    const int cAadd = (Am >> 1) * 8 + Ar;
    const int Br  = lane & 7;
    const int Bc  = (lane >> 3) & 1;
    const int Bnt = lane >> 4;

#pragma unroll
    for (int k = 0; k < 4; k++) {
        int cA = k*16 + cAadd;
        uint32_t offA = cA*256 + ((((sA >> 3) ^ (cA & 7)) << 4));
        uint32_t ah[4], al[4];
        ldmA_t(ah, aHiB + offA);
        ldmA_t(al, aLoB + offA);
        int cB = k*16 + Bc*8;
#pragma unroll
        for (int ntp = 0; ntp < NOUT/16; ntp++) {
            int oRow = (2*ntp + Bnt)*8 + Br;
            uint32_t offB = oRow*128 + ((((cB >> 3) ^ (oRow & 7)) << 4));
            uint32_t bh[4], bl[4];
            ldmB4(bh, bHiB + offB);
            ldmB4(bl, bLoB + offB);
            mma_bf16(acc[2*ntp],   ah, bh);
            mma_bf16(acc[2*ntp],   ah, bl);
            mma_bf16(acc[2*ntp],   al, bh);
            mma_bf16(acc[2*ntp+1], ah, bh + 2);
            mma_bf16(acc[2*ntp+1], ah, bl + 2);
            mma_bf16(acc[2*ntp+1], al, bh + 2);
        }
    }

    mma_epilogue<NOUT, DO_MAX>(acc, sbias, smx, smn, Hout, bx);
}

// ---------------- stats reduce ------------------------------------------------
__global__ void k_reduce2(const float* __restrict__ gam, const float* __restrict__ bet,
                          int count) {
    __shared__ float s1[256], s2[256];
    const int c = blockIdx.x;
    const int t = threadIdx.x;
    const float* p1 = g_ps1 + (size_t)c*PSW;
    const float* p2 = g_ps2 + (size_t)c*PSW;
    float a = 0.f, b = 0.f;
    for (int i = t; i < count; i += 256) { a += p1[i]; b += p2[i]; }
    s1[t] = a; s2[t] = b;
    __syncthreads();
#pragma unroll
    for (int d = 128; d; d >>= 1) {
        if (t < d) { s1[t] += s1[t+d]; s2[t] += s2[t+d]; }
        __syncthreads();
    }
    if (t == 0) {
        const float inv = 1.0f / (float)STOT;
        float mu  = s1[0] * inv;
        float var = s2[0] * inv - mu * mu;
        float sc  = gam[c] * rsqrtf(var + EPSBN);
        g_scale[c] = sc;
        g_shift[c] = bet[c] - mu * sc;
    }
}

// ---------------- finalize: affine extreme + relu -> out (B,C2,M) -------------
__global__ void k_finalmax(float* __restrict__ out) {
    const int t = blockIdx.x * 256 + threadIdx.x;
    const int m = t & 1023;
    const int c = (t >> 10) & 127;
    const int b = t >> 17;
    const int qidx = (b << 10) + m;
    const float sc = g_scale[c], sh = g_shift[c];
    float ext = (sc >= 0.0f) ? g_hmax[(size_t)c*NQ + qidx] : g_hmin[(size_t)c*NQ + qidx];
    float v = fmaxf(fmaf(ext, sc, sh), 0.0f);
    out[(size_t)BB*MM*3 + (((size_t)b*C2 + c) << 10) + m] = v;
}

// ---------------- launch --------------------------------------------------------
extern "C" void kernel_launch(void* const* d_in, const int* in_sizes, int n_in,
                              void* d_out, int out_size) {
    const float* p   = (const float*)d_in[0];
    const float* q   = (const float*)d_in[1];
    const float* x   = (const float*)d_in[2];
    const float* W0  = (const float*)d_in[3];
    const float* b0  = (const float*)d_in[4];
    const float* g0  = (const float*)d_in[5];
    const float* be0 = (const float*)d_in[6];
    const float* W1  = (const float*)d_in[7];
    const float* b1  = (const float*)d_in[8];
    const float* g1  = (const float*)d_in[9];
    const float* be1 = (const float*)d_in[10];
    const float* W2  = (const float*)d_in[11];
    const float* b2  = (const float*)d_in[12];
    const float* g2  = (const float*)d_in[13];
    const float* be2 = (const float*)d_in[14];
    float* out = (float*)d_out;

    float *h0p, *h1p;
    cudaGetSymbolAddress((void**)&h0p, g_h0);
    cudaGetSymbolAddress((void**)&h1p, g_h1);

    const int bq_smem = NN*3*4 + 8*KK*4;
    const int m0_smem = 2*80*256 + 2*64*256 + 64*4;               // 74240
    const int m1_smem = 2*64*128*2 + 2*64*64*2 + (64+128)*4 + 2*8*64*4;
    const int m2_smem = 2*64*128*2 + 2*128*64*2 + (128+128)*4 + 2*8*128*4;
    cudaFuncSetAttribute(k_ballquery, cudaFuncAttributeMaxDynamicSharedMemorySize, bq_smem);
    cudaFuncSetAttribute(k_mma0, cudaFuncAttributeMaxDynamicSharedMemorySize, m0_smem);
    cudaFuncSetAttribute((const void*)k_mma<64,false>,  cudaFuncAttributeMaxDynamicSharedMemorySize, m1_smem);
    cudaFuncSetAttribute((const void*)k_mma<128,true>,  cudaFuncAttributeMaxDynamicSharedMemorySize, m2_smem);

    k_transpose<<<dim3(NN/32, CF/32, BB), dim3(32, 8)>>>(x);
    k_copyq<<<(BB*MM*3)/256, 256>>>(q, out);
    k_ballquery<<<dim3(MM/8, BB), 256, bq_smem>>>(p, q);

    k_mma0<<<NMB, 256, m0_smem>>>(p, q, W0, b0);
    k_reduce2<<<C0, 256>>>(g0, be0, PSW);

    k_mma<64,false><<<NMB, 256, m1_smem>>>(h0p, h1p, W1, b1);
    k_reduce2<<<C1, 256>>>(g1, be1, PSW);

    k_mma<128,true><<<NMB, 256, m2_smem>>>(h1p, nullptr, W2, b2);
    k_reduce2<<<C2, 256>>>(g2, be2, PSW);

    k_finalmax<<<(BB*C2*MM)/256, 256>>>(out);
}